// round 1
// baseline (speedup 1.0000x reference)
#include <cuda_runtime.h>
#include <math.h>

// Problem constants
#define B_    64
#define L_    256
#define D_    128
#define N_    8192
#define KEEP_ 64
#define HID_  1024
// W1 rows: [0,128) = q, [128, 128+8192) = packed keys, row 8320 = log_count

// GEMM tiling
#define BM 64
#define BN 64
#define BKc 64
#define NCHUNK 130   // 130 * 64 = 8320 rows of W1; row 8320 handled in epilogue

// Scratch (allocation-free rule: __device__ globals)
__device__ int   g_idx[N_ * KEEP_];
__device__ float g_hact[(size_t)N_ * HID_];
__device__ int   g_mask_mode;   // 0 = uint8, 1 = int32, 2 = float32

// ---------------------------------------------------------------------------
// Sniff the storage type of the bool mask (harness dtype for bool is ambiguous).
// int32 0/1 -> words in {0,1}; float32 0/1 -> words in {0, 0x3F800000};
// uint8 packed bools -> random byte patterns, neither property holds.
// Deterministic for fixed input.
// ---------------------------------------------------------------------------
__global__ void detect_mask_kernel(const unsigned int* __restrict__ mw) {
    if (threadIdx.x != 0 || blockIdx.x != 0) return;
    bool i32ok = true, f32ok = true;
    for (int i = 0; i < 1024; i++) {         // 4 KB, always within buffer
        unsigned w = mw[i];
        if (!(w == 0u || w == 1u)) i32ok = false;
        if (!(w == 0u || w == 0x3F800000u)) f32ok = false;
    }
    g_mask_mode = i32ok ? 1 : (f32ok ? 2 : 0);
}

// ---------------------------------------------------------------------------
// One warp per row: collect the first <=64 masked positions in ascending
// order (== jax top_k on mask*(L-pos) + sort). Sentinel -1 for empty slots.
// ---------------------------------------------------------------------------
__global__ void gather_idx_kernel(const void* __restrict__ maskp) {
    int gw   = (blockIdx.x * blockDim.x + threadIdx.x) >> 5;
    int lane = threadIdx.x & 31;
    if (gw >= N_) return;
    const int n = gw;

    g_idx[n * KEEP_ + lane]      = -1;
    g_idx[n * KEEP_ + 32 + lane] = -1;
    __syncwarp();

    const int mode = g_mask_mode;
    const unsigned char* m8  = (const unsigned char*)maskp;
    const int*           m32 = (const int*)maskp;
    const float*         mf  = (const float*)maskp;

    int base = 0;
    for (int g = 0; g < 8 && base < KEEP_; g++) {
        int pos = g * 32 + lane;
        bool m;
        if (mode == 1)      m = (m32[(size_t)n * L_ + pos] != 0);
        else if (mode == 2) m = (mf [(size_t)n * L_ + pos] != 0.0f);
        else                m = (m8 [(size_t)n * L_ + pos] != 0);
        unsigned bal = __ballot_sync(0xffffffffu, m);
        int slot = base + __popc(bal & ((1u << lane) - 1u));
        if (m && slot < KEEP_) g_idx[n * KEEP_ + slot] = pos;
        base += __popc(bal);
    }
}

__device__ __forceinline__ float gelu_exact(float x) {
    return 0.5f * x * (1.0f + erff(x * 0.7071067811865476f));
}

// ---------------------------------------------------------------------------
// Layer-1 GEMM with implicit A gather.
// Block computes a [64 x 64] tile of z = feat @ W1; loops 130 chunks of K=64.
// A chunk rows come from q (chunks 0..1) or gathered key rows (2 chunks per
// key, zero-filled when idx == -1). Epilogue: + b1 + log1p(count)*W1[8320,:],
// exact GELU, store h to scratch.
// ---------------------------------------------------------------------------
__global__ void __launch_bounds__(256)
mlp1_kernel(const float* __restrict__ q, const float* __restrict__ kmat,
            const int* __restrict__ batch_idx, const int* __restrict__ count,
            const float* __restrict__ W1, const float* __restrict__ b1)
{
    __shared__ float As[BKc][BM];   // transposed: As[k][m]
    __shared__ float Bs[BKc][BN];
    __shared__ float lc_s[BM];

    const int t  = threadIdx.x;
    const int tx = t & 15;          // 16 col-groups of 4
    const int ty = t >> 4;          // 16 row-groups of 4
    const int m0 = blockIdx.y * BM;
    const int n0 = blockIdx.x * BN;

    // A-loader role: each thread owns row (t&63), quarter (t>>6) of the K range
    const int ar   = t & 63;
    const int aq   = t >> 6;        // 0..3 -> k offsets aq*16 .. aq*16+15
    const int arow = m0 + ar;
    const float* krow0  = kmat + (size_t)batch_idx[arow] * (L_ * D_);
    const float* qrow   = q + (size_t)arow * D_;
    const int*   idxrow = g_idx + (size_t)arow * KEEP_;

    if (t < BM) lc_s[t] = log1pf((float)count[m0 + t]);

    float acc[4][4];
#pragma unroll
    for (int i = 0; i < 4; i++)
#pragma unroll
        for (int j = 0; j < 4; j++) acc[i][j] = 0.0f;

    for (int c = 0; c < NCHUNK; c++) {
        // ---- gather A chunk into smem (transposed) ----
        const float* src = 0;
        if (c < 2) {
            src = qrow + c * 64;
        } else {
            int j   = (c - 2) >> 1;
            int idx = idxrow[j];
            if (idx >= 0) src = krow0 + (size_t)idx * D_ + ((c - 2) & 1) * 64;
        }
#pragma unroll
        for (int i = 0; i < 4; i++) {
            int kk = aq * 16 + i * 4;
            float4 v = src ? *(const float4*)(src + kk)
                           : make_float4(0.f, 0.f, 0.f, 0.f);
            As[kk + 0][ar] = v.x;
            As[kk + 1][ar] = v.y;
            As[kk + 2][ar] = v.z;
            As[kk + 3][ar] = v.w;
        }
        // ---- load B chunk: W1 rows [c*64, c*64+64), cols [n0, n0+64) ----
        const float* wbase = W1 + (size_t)c * BKc * HID_ + n0;
#pragma unroll
        for (int i = 0; i < 4; i++) {
            int kr = i * 16 + ty;
            *(float4*)&Bs[kr][tx * 4] =
                *(const float4*)(wbase + (size_t)kr * HID_ + tx * 4);
        }
        __syncthreads();

#pragma unroll 16
        for (int kk = 0; kk < BKc; kk++) {
            float4 a = *(const float4*)&As[kk][ty * 4];
            float4 b = *(const float4*)&Bs[kk][tx * 4];
            acc[0][0] += a.x*b.x; acc[0][1] += a.x*b.y; acc[0][2] += a.x*b.z; acc[0][3] += a.x*b.w;
            acc[1][0] += a.y*b.x; acc[1][1] += a.y*b.y; acc[1][2] += a.y*b.z; acc[1][3] += a.y*b.w;
            acc[2][0] += a.z*b.x; acc[2][1] += a.z*b.y; acc[2][2] += a.z*b.z; acc[2][3] += a.z*b.w;
            acc[3][0] += a.w*b.x; acc[3][1] += a.w*b.y; acc[3][2] += a.w*b.z; acc[3][3] += a.w*b.w;
        }
        __syncthreads();
    }

    // ---- epilogue: bias + log_count feature + exact GELU, store h ----
    const float4 wl = *(const float4*)(W1 + (size_t)8320 * HID_ + n0 + tx * 4);
    const float4 bb = *(const float4*)(b1 + n0 + tx * 4);
#pragma unroll
    for (int i = 0; i < 4; i++) {
        int   row = m0 + ty * 4 + i;
        float lc  = lc_s[ty * 4 + i];
        float4 z;
        z.x = acc[i][0] + bb.x + lc * wl.x;
        z.y = acc[i][1] + bb.y + lc * wl.y;
        z.z = acc[i][2] + bb.z + lc * wl.z;
        z.w = acc[i][3] + bb.w + lc * wl.w;
        z.x = gelu_exact(z.x); z.y = gelu_exact(z.y);
        z.z = gelu_exact(z.z); z.w = gelu_exact(z.w);
        *(float4*)&g_hact[(size_t)row * HID_ + n0 + tx * 4] = z;
    }
}

// ---------------------------------------------------------------------------
// Layer 2: out[n] = h[n,:] @ W2 + b2. One block per row; deterministic tree
// reduction (no atomics).
// ---------------------------------------------------------------------------
__global__ void __launch_bounds__(256)
reduce_kernel(const float* __restrict__ W2, const float* __restrict__ b2,
              float* __restrict__ out)
{
    const int n = blockIdx.x;
    const int t = threadIdx.x;
    const float4 hv = ((const float4*)(g_hact + (size_t)n * HID_))[t];
    const float4 wv = ((const float4*)W2)[t];
    float s = hv.x*wv.x + hv.y*wv.y + hv.z*wv.z + hv.w*wv.w;

#pragma unroll
    for (int o = 16; o > 0; o >>= 1) s += __shfl_xor_sync(0xffffffffu, s, o);

    __shared__ float ws[8];
    if ((t & 31) == 0) ws[t >> 5] = s;
    __syncthreads();
    if (t < 8) {
        s = ws[t];
#pragma unroll
        for (int o = 4; o > 0; o >>= 1) s += __shfl_xor_sync(0xffu, s, o);
        if (t == 0) out[n] = s + b2[0];
    }
}

// ---------------------------------------------------------------------------
extern "C" void kernel_launch(void* const* d_in, const int* in_sizes, int n_in,
                              void* d_out, int out_size) {
    const float* q     = (const float*)d_in[0];
    const float* k     = (const float*)d_in[1];
    const int*   bidx  = (const int*)d_in[2];
    const void*  mask  = d_in[3];
    const int*   count = (const int*)d_in[4];
    const float* W1    = (const float*)d_in[5];
    const float* b1    = (const float*)d_in[6];
    const float* W2    = (const float*)d_in[7];
    const float* b2    = (const float*)d_in[8];
    float* out = (float*)d_out;

    detect_mask_kernel<<<1, 32>>>((const unsigned int*)mask);
    gather_idx_kernel<<<N_ / 8, 256>>>(mask);

    dim3 grid(HID_ / BN, N_ / BM);   // (16, 128) = 2048 blocks
    mlp1_kernel<<<grid, 256>>>(q, k, bidx, count, W1, b1);

    reduce_kernel<<<N_, 256>>>(W2, b2, out);
}